// round 15
// baseline (speedup 1.0000x reference)
#include <cuda_runtime.h>
#include <cuda_fp16.h>
#include <math.h>
#include <stdint.h>

typedef __half f16;

#define BQ 2
#define TQ 2048
#define DMODEL 1024
#define DINNER 2048
#define NHEADS 32
#define DHEAD 64
#define DCONV 4
#define PROJ_OUT 4224
#define BT 4096
#define PARAM_OFF 4096
#define BC_OFF 4160
#define DFF 4096

// ---------------- scratch (device globals; no allocation) ----------------
__device__ float g_proj[(size_t)BT * PROJ_OUT];
__device__ float g_val [(size_t)BT * DINNER];
__device__ float g_par [(size_t)BT * NHEADS * 2];
__device__ float g_bcT [(size_t)BT * 64];
__device__ float g_scan[(size_t)BT * DINNER];
__device__ float g_x1  [BT * DMODEL];
// fp16 activations
__device__ f16 g_h1h[BT * DMODEL],         g_h1l[BT * DMODEL];
__device__ f16 g_ygh[(size_t)BT * DINNER];
__device__ f16 g_h2h[BT * DMODEL];
__device__ f16 g_ffh[(size_t)BT * DFF];
// fp16 weights (hi only)
__device__ f16 g_win[PROJ_OUT * 1024];
__device__ f16 g_wo [1024 * 2048];
__device__ f16 g_w1 [4096 * 1024];
__device__ f16 g_w2 [1024 * 4096];
// fp16 hi/lo split of w_in tail rows (4096..4223) for high-precision scan params
__device__ f16 g_wth[128 * 1024], g_wtl[128 * 1024];

// ---------------- math helpers ----------------
__device__ __forceinline__ float siluf_(float x)    { return x / (1.f + __expf(-x)); }
__device__ __forceinline__ float geluf_(float x) {
    float x3 = x * x * x;
    return 0.5f * x * (1.f + tanhf(0.7978845608028654f * (x + 0.044715f * x3)));
}
__device__ __forceinline__ float sigmoidf_(float x) { return 1.f / (1.f + __expf(-x)); }
__device__ __forceinline__ float softplusf_(float x) {
    return (x > 20.f) ? x : log1pf(expf(x));
}
__device__ __forceinline__ void split1(float v, f16* h, f16* l) {
    f16 hh = __float2half_rn(v);
    *h = hh;
    *l = __float2half_rn(v - __half2float(hh));
}

__device__ __forceinline__ float block_reduce_sum(float v) {
    __shared__ float sh[32];
    int lane = threadIdx.x & 31, wid = threadIdx.x >> 5;
    int nwarps = blockDim.x >> 5;
    #pragma unroll
    for (int m = 16; m > 0; m >>= 1) v += __shfl_xor_sync(0xffffffffu, v, m);
    if (lane == 0) sh[wid] = v;
    __syncthreads();
    if (wid == 0) {
        v = (lane < nwarps) ? sh[lane] : 0.f;
        #pragma unroll
        for (int m = 16; m > 0; m >>= 1) v += __shfl_xor_sync(0xffffffffu, v, m);
        if (lane == 0) sh[0] = v;
    }
    __syncthreads();
    return sh[0];
}

// ---------------- low-level (sm_80-compatible only) ----------------
__device__ __forceinline__ uint32_t smem_u32(const void* p) {
    uint32_t a;
    asm("{ .reg .u64 t; cvta.to.shared.u64 t, %1; cvt.u32.u64 %0, t; }" : "=r"(a) : "l"(p));
    return a;
}
#define CP_ASYNC16(dst, src) \
    asm volatile("cp.async.cg.shared.global [%0], [%1], 16;" :: "r"((uint32_t)(dst)), "l"(src))
#define CP_COMMIT() asm volatile("cp.async.commit_group;" ::: "memory")

__device__ __forceinline__ void ldsm_x4(uint32_t* r, uint32_t addr) {
    asm volatile("ldmatrix.sync.aligned.m8n8.x4.shared.b16 {%0,%1,%2,%3}, [%4];"
                 : "=r"(r[0]), "=r"(r[1]), "=r"(r[2]), "=r"(r[3]) : "r"(addr));
}
__device__ __forceinline__ void ldsm_x2(uint32_t* r, uint32_t addr) {
    asm volatile("ldmatrix.sync.aligned.m8n8.x2.shared.b16 {%0,%1}, [%2];"
                 : "=r"(r[0]), "=r"(r[1]) : "r"(addr));
}
__device__ __forceinline__ void mma16816(float* c, const uint32_t* a, const uint32_t* b) {
    asm volatile("mma.sync.aligned.m16n8k16.row.col.f32.f16.f16.f32 "
                 "{%0,%1,%2,%3}, {%4,%5,%6,%7}, {%8,%9}, {%0,%1,%2,%3};"
                 : "+f"(c[0]), "+f"(c[1]), "+f"(c[2]), "+f"(c[3])
                 : "r"(a[0]), "r"(a[1]), "r"(a[2]), "r"(a[3]), "r"(b[0]), "r"(b[1]));
}

// ---------------- rmsnorm + fp16 (optional lo) (D=1024, 256 thr) ----------------
__global__ void rmsnorm_split_kernel(const float* __restrict__ x, const float* __restrict__ w,
                                     f16* __restrict__ oh, f16* __restrict__ ol) {
    int row = blockIdx.x;
    int i = threadIdx.x;
    const float4* xr = (const float4*)(x + (size_t)row * DMODEL);
    float4 v = xr[i];
    float ss = v.x * v.x + v.y * v.y + v.z * v.z + v.w * v.w;
    ss = block_reduce_sum(ss);
    float inv = rsqrtf(ss / (float)DMODEL + 1e-6f);
    float4 wv = ((const float4*)w)[i];
    float o0 = v.x * inv * wv.x, o1 = v.y * inv * wv.y;
    float o2 = v.z * inv * wv.z, o3 = v.w * inv * wv.w;
    __half2 h0, h1, l0, l1;
    split1(o0, &h0.x, &l0.x); split1(o1, &h0.y, &l0.y);
    split1(o2, &h1.x, &l1.x); split1(o3, &h1.y, &l1.y);
    __half2* ohp = (__half2*)(oh + (size_t)row * DMODEL);
    ohp[2 * i] = h0; ohp[2 * i + 1] = h1;
    if (ol) {
        __half2* olp = (__half2*)(ol + (size_t)row * DMODEL);
        olp[2 * i] = l0; olp[2 * i + 1] = l1;
    }
}

// ---------------- gated rmsnorm -> fp16 hi only (DINNER=2048) ----------------
__global__ void gated_norm_kernel(const float* __restrict__ proj, const float* __restrict__ scan_y,
                                  const float* __restrict__ w, f16* __restrict__ oh) {
    int row = blockIdx.x;
    int tid = threadIdx.x;
    const float4* prow = (const float4*)(proj + (size_t)row * PROJ_OUT);
    const float4* sy = (const float4*)(scan_y + (size_t)row * DINNER);
    float4 tv[2];
    float ss = 0.f;
    #pragma unroll
    for (int q = 0; q < 2; ++q) {
        int i = tid + q * 256;
        float4 g = prow[i];
        float4 s = sy[i];
        float4 t;
        t.x = s.x * siluf_(g.x); t.y = s.y * siluf_(g.y);
        t.z = s.z * siluf_(g.z); t.w = s.w * siluf_(g.w);
        tv[q] = t;
        ss += t.x * t.x + t.y * t.y + t.z * t.z + t.w * t.w;
    }
    ss = block_reduce_sum(ss);
    float inv = rsqrtf(ss / (float)DINNER + 1e-6f);
    __half2* ohp = (__half2*)(oh + (size_t)row * DINNER);
    #pragma unroll
    for (int q = 0; q < 2; ++q) {
        int i = tid + q * 256;
        float4 wv = ((const float4*)w)[i];
        __half2 h0, h1;
        h0.x = __float2half_rn(tv[q].x * inv * wv.x);
        h0.y = __float2half_rn(tv[q].y * inv * wv.y);
        h1.x = __float2half_rn(tv[q].z * inv * wv.z);
        h1.y = __float2half_rn(tv[q].w * inv * wv.w);
        ohp[2 * i] = h0; ohp[2 * i + 1] = h1;
    }
}

// ---------------- fp32 -> fp16 convert, MLP-4 grid-stride ----------------
__global__ void cvt16_kernel(const float4* __restrict__ src, __half2* __restrict__ dst, int n4) {
    int i = blockIdx.x * blockDim.x + threadIdx.x;
    int stride = gridDim.x * blockDim.x;
    float4 v[4];
    int idx[4];
    #pragma unroll
    for (int q = 0; q < 4; ++q) {
        idx[q] = i + q * stride;
        if (idx[q] < n4) v[q] = src[idx[q]];
    }
    #pragma unroll
    for (int q = 0; q < 4; ++q) {
        if (idx[q] < n4) {
            __half2 h0, h1;
            h0.x = __float2half_rn(v[q].x); h0.y = __float2half_rn(v[q].y);
            h1.x = __float2half_rn(v[q].z); h1.y = __float2half_rn(v[q].w);
            dst[2 * idx[q]] = h0; dst[2 * idx[q] + 1] = h1;
        }
    }
}

// ---------------- fp32 -> fp16 hi/lo split (vectorized) ----------------
__global__ void split4_kernel(const float4* __restrict__ src, __half2* __restrict__ hi,
                              __half2* __restrict__ lo, int n4) {
    int i = blockIdx.x * blockDim.x + threadIdx.x;
    if (i >= n4) return;
    float4 v = src[i];
    __half2 h0, h1, l0, l1;
    split1(v.x, &h0.x, &l0.x); split1(v.y, &h0.y, &l0.y);
    split1(v.z, &h1.x, &l1.x); split1(v.w, &h1.y, &l1.y);
    hi[2 * i] = h0; hi[2 * i + 1] = h1;
    lo[2 * i] = l0; lo[2 * i + 1] = l1;
}

// ---------------- fused conv+silu / params / bcpack (one block per (b,t)) ----------------
__global__ void prep_kernel(const float* __restrict__ proj, const float* __restrict__ conv_w,
                            const float* __restrict__ conv_b, float* __restrict__ value,
                            float* __restrict__ par, float* __restrict__ bcT) {
    int bt = blockIdx.x;
    int t = bt & (TQ - 1);
    int tid = threadIdx.x;
    const float* prow = proj + (size_t)bt * PROJ_OUT;
    #pragma unroll
    for (int i = 0; i < 8; ++i) {
        int c = tid + i * 256;
        float acc = conv_b[c];
        #pragma unroll
        for (int k = 0; k < DCONV; ++k) {
            int ts = t - (DCONV - 1) + k;
            if (ts >= 0)
                acc += prow[(ts - t) * (ptrdiff_t)PROJ_OUT + DINNER + c] * conv_w[c * DCONV + k];
        }
        value[(size_t)bt * DINNER + c] = siluf_(acc);
    }
    if (tid < 32) {
        int h = tid;
        par[((size_t)bt * NHEADS + h) * 2 + 0] = softplusf_(prow[PARAM_OFF + 2 * h]);
        par[((size_t)bt * NHEADS + h) * 2 + 1] = sigmoidf_(prow[PARAM_OFF + 2 * h + 1]);
    } else if (tid >= 64 && tid < 80) {
        int n = tid - 64;
        float4 v;
        v.x = prow[BC_OFF + n];
        v.y = prow[BC_OFF + 16 + n];
        v.z = prow[BC_OFF + 32 + n];
        v.w = prow[BC_OFF + 48 + n];
        ((float4*)bcT)[(size_t)bt * 16 + n] = v;
    }
}

// ---------------- sequential SSM scan (n-pair per thread; 256 thr/block) ----------------
// block = (b, h, p-half); thread = 32 p x 8 n-groups, each covering n and n+8.
__global__ void scan_kernel(const float* __restrict__ bcT, const float* __restrict__ par,
                            const float* __restrict__ value, float* __restrict__ scan_y) {
    int blk = blockIdx.x;
    int bh = blk >> 1;
    int b = bh >> 5;
    int h = bh & 31;
    int half = blk & 1;
    int tid = threadIdx.x;
    int p = half * 32 + (tid >> 3);
    int nlo = tid & 7;
    float S0a = 0.f, S1a = 0.f, S0b = 0.f, S1b = 0.f;
    const size_t rowbase = (size_t)b * TQ;
    const float4* pbc = (const float4*)bcT + rowbase * 16 + nlo;
    const float2* pad = (const float2*)par + rowbase * NHEADS + h;
    const float*  pu  = value + rowbase * DINNER + h * DHEAD + p;
    float*        py  = scan_y + rowbase * DINNER + h * DHEAD + p;
    float4 nb0 = pbc[0], nb1 = pbc[8];
    float2 nad = *pad;
    float  nu  = *pu;
    for (int t = 0; t < TQ; ++t) {
        float4 b0 = nb0, b1 = nb1;
        float2 ad = nad;
        float u = nu;
        if (t + 1 < TQ) {
            pbc += 16; pad += NHEADS; pu += DINNER;
            nb0 = pbc[0]; nb1 = pbc[8];
            nad = *pad; nu = *pu;
        }
        float A = ad.x, dt = ad.y;
        float dtA = dt * A;
        float du = dt * u;
        float c1 = 1.f - dt * dtA;
        float s0a = fmaf(-dtA, S1a, fmaf(b0.x, du, S0a));
        float s1a = fmaf(dt, S0a, fmaf(c1, S1a, dt * b0.y * du));
        float s0b = fmaf(-dtA, S1b, fmaf(b1.x, du, S0b));
        float s1b = fmaf(dt, S0b, fmaf(c1, S1b, dt * b1.y * du));
        S0a = s0a; S1a = s1a; S0b = s0b; S1b = s1b;
        float y = b0.z * s0a + b0.w * s1a + b1.z * s0b + b1.w * s1b;
        y += __shfl_xor_sync(0xffffffffu, y, 4);
        y += __shfl_xor_sync(0xffffffffu, y, 2);
        y += __shfl_xor_sync(0xffffffffu, y, 1);
        if (nlo == 0) *py = y;
        py += DINNER;
    }
}

#define TILEB 10240                 // 128 rows x 80B

// ---------------- fp16 1-product GEMM: 3-stage, single sync per chunk ----------------
// mode 1: C = acc + bias? + res? (fp32) ; mode 2: Oh = fp16(gelu(acc + bias))
#define STAGEB1 (2 * TILEB)
#define GEMM1_SMEM (3 * STAGEB1)    // 61440
__global__ void __launch_bounds__(256, 2)
gemm_mma1(const f16* __restrict__ Ah, const f16* __restrict__ Bh,
          const float* __restrict__ bias, const float* __restrict__ res,
          float* __restrict__ C, f16* __restrict__ Oh,
          int N, int K, int mode) {
    extern __shared__ __align__(16) f16 dsm[];
    const uint32_t s0 = smem_u32(dsm);
    const int tid = threadIdx.x, wid = tid >> 5, lane = tid & 31;
    const int row0 = blockIdx.y * 128, col0 = blockIdx.x * 128;
    const int wm = wid & 1, wn = wid >> 1;
    const int nch = K >> 5;

    float acc[4][4][4];
    #pragma unroll
    for (int mt = 0; mt < 4; ++mt)
        #pragma unroll
        for (int nt = 0; nt < 4; ++nt)
            #pragma unroll
            for (int q = 0; q < 4; ++q) acc[mt][nt][q] = 0.f;

    const int lr = tid >> 2, lc = tid & 3;
    const f16* gAh = Ah + (size_t)(row0 + lr) * K + lc * 8;
    const f16* gBh = Bh + (size_t)(col0 + lr) * K + lc * 8;
    const uint32_t dst = lr * 80 + lc * 16;

    #define LOAD_CHUNK1(stg, k0) do {                                                  \
        uint32_t _b = s0 + (stg) * STAGEB1 + dst;                                      \
        CP_ASYNC16(_b,                   gAh + (k0));                                  \
        CP_ASYNC16(_b + 64 * 80,         gAh + (size_t)64 * K + (k0));                 \
        CP_ASYNC16(_b + TILEB,           gBh + (k0));                                  \
        CP_ASYNC16(_b + TILEB + 64 * 80, gBh + (size_t)64 * K + (k0));                 \
        CP_COMMIT();                                                                   \
    } while (0)

    LOAD_CHUNK1(0, 0);
    LOAD_CHUNK1(1, 32);

    const uint32_t a_row = (uint32_t)(wm * 64 + (lane & 15));
    const uint32_t a_coff = (uint32_t)((lane >> 4) * 8);
    const uint32_t b_row2 = (uint32_t)(wn * 32 + (lane & 7) + (((lane >> 4) & 1) << 3));
    const uint32_t b_coff = (uint32_t)(((lane >> 3) & 1) * 8);

    for (int ch = 0; ch < nch; ++ch) {
        if (ch + 1 < nch)
            asm volatile("cp.async.wait_group 1;" ::: "memory");
        else
            asm volatile("cp.async.wait_group 0;" ::: "memory");
        __syncthreads();
        if (ch + 2 < nch)
            LOAD_CHUNK1((ch + 2) % 3, (ch + 2) << 5);

        const uint32_t sb = s0 + (ch % 3) * STAGEB1;
        const uint32_t sAh_ = sb, sBh_ = sb + TILEB;
        #pragma unroll
        for (int ks = 0; ks < 2; ++ks) {
            const uint32_t acol = (ks * 16 + a_coff) * 2;
            const uint32_t bcol = (ks * 16 + b_coff) * 2;
            uint32_t afr[4][4], bfr[4][2];
            #pragma unroll
            for (int q = 0; q < 2; ++q) {
                uint32_t tmp[4];
                ldsm_x4(tmp, sBh_ + (b_row2 + q * 16) * 80 + bcol);
                bfr[2 * q][0] = tmp[0]; bfr[2 * q][1] = tmp[1];
                bfr[2 * q + 1][0] = tmp[2]; bfr[2 * q + 1][1] = tmp[3];
            }
            #pragma unroll
            for (int mt = 0; mt < 4; ++mt)
                ldsm_x4(afr[mt], sAh_ + (a_row + mt * 16) * 80 + acol);
            #pragma unroll
            for (int mt = 0; mt < 4; ++mt)
                #pragma unroll
                for (int nt = 0; nt < 4; ++nt)
                    mma16816(acc[mt][nt], afr[mt], bfr[nt]);
        }
    }

    const int er = lane >> 2, ec = (lane & 3) << 1;
    #pragma unroll
    for (int mt = 0; mt < 4; ++mt) {
        #pragma unroll
        for (int nt = 0; nt < 4; ++nt) {
            int gr = row0 + wm * 64 + mt * 16 + er;
            int gc = col0 + wn * 32 + nt * 8 + ec;
            const float* cc = acc[mt][nt];
            #pragma unroll
            for (int half = 0; half < 2; ++half) {
                int r = gr + half * 8;
                float v0 = cc[half * 2 + 0], v1 = cc[half * 2 + 1];
                if (mode == 2) {
                    v0 = geluf_(v0 + bias[gc]);
                    v1 = geluf_(v1 + bias[gc + 1]);
                    __half2 hp;
                    hp.x = __float2half_rn(v0);
                    hp.y = __float2half_rn(v1);
                    *(__half2*)(Oh + (size_t)r * N + gc) = hp;
                } else {
                    if (bias) { v0 += bias[gc]; v1 += bias[gc + 1]; }
                    if (res) {
                        const float* rp = res + (size_t)r * N + gc;
                        v0 += rp[0]; v1 += rp[1];
                    }
                    float2 v; v.x = v0; v.y = v1;
                    *(float2*)(C + (size_t)r * N + gc) = v;
                }
            }
        }
    }
}

// ---------------- fp16 3-product GEMM (high precision; in-proj tail) ----------------
#define STAGEB3 (4 * TILEB)
#define GEMM3_SMEM (2 * STAGEB3)
__global__ void __launch_bounds__(256, 2)
gemm_mma3(const f16* __restrict__ Ah, const f16* __restrict__ Al,
          const f16* __restrict__ Bh, const f16* __restrict__ Bl,
          float* __restrict__ C, int ldN, int K) {
    extern __shared__ __align__(16) f16 dsm[];
    const uint32_t s0 = smem_u32(dsm);
    const int tid = threadIdx.x, wid = tid >> 5, lane = tid & 31;
    const int row0 = blockIdx.y * 128, col0 = blockIdx.x * 128;
    const int wm = wid & 1, wn = wid >> 1;
    const int nch = K >> 5;

    float acc[4][4][4];
    #pragma unroll
    for (int mt = 0; mt < 4; ++mt)
        #pragma unroll
        for (int nt = 0; nt < 4; ++nt)
            #pragma unroll
            for (int q = 0; q < 4; ++q) acc[mt][nt][q] = 0.f;

    const int lr = tid >> 2, lc = tid & 3;
    const f16* gAh = Ah + (size_t)(row0 + lr) * K + lc * 8;
    const f16* gAl = Al + (size_t)(row0 + lr) * K + lc * 8;
    const f16* gBh = Bh + (size_t)(col0 + lr) * K + lc * 8;
    const f16* gBl = Bl + (size_t)(col0 + lr) * K + lc * 8;
    const uint32_t dst = lr * 80 + lc * 16;

    #define LOAD_CHUNK3(stg, k0) do {                                                  \
        uint32_t _b = s0 + (stg) * STAGEB3 + dst;                                      \
        CP_ASYNC16(_b,                       gAh + (k0));                              \
        CP_ASYNC16(_b + 64 * 80,             gAh + (size_t)64 * K + (k0));             \
        CP_ASYNC16(_b + TILEB,               gAl + (k0));                              \
        CP_ASYNC16(_b + TILEB + 64 * 80,     gAl + (size_t)64 * K + (k0));             \
        CP_ASYNC16(_b + 2 * TILEB,           gBh + (k0));                              \
        CP_ASYNC16(_b + 2 * TILEB + 64 * 80, gBh + (size_t)64 * K + (k0));             \
        CP_ASYNC16(_b + 3 * TILEB,           gBl + (k0));                              \
        CP_ASYNC16(_b + 3 * TILEB + 64 * 80, gBl + (size_t)64 * K + (k0));             \
        CP_COMMIT();                                                                   \
    } while (0)

    LOAD_CHUNK3(0, 0);

    const uint32_t a_row = (uint32_t)(wm * 64 + (lane & 15));
    const uint32_t a_coff = (uint32_t)((lane >> 4) * 8);
    const uint32_t b_row = (uint32_t)(wn * 32 + (lane & 7));
    const uint32_t b_coff = (uint32_t)(((lane >> 3) & 1) * 8);

    for (int ch = 0; ch < nch; ++ch) {
        const int stg = ch & 1;
        if (ch + 1 < nch) {
            LOAD_CHUNK3(stg ^ 1, (ch + 1) << 5);
            asm volatile("cp.async.wait_group 1;" ::: "memory");
        } else {
            asm volatile("cp.async.wait_group 0;" ::: "memory");
        }
        __syncthreads();

        const uint32_t sb = s0 + stg * STAGEB3;
        const uint32_t sAh_ = sb, sAl_ = sb + TILEB, sBh_ = sb + 2 * TILEB, sBl_ = sb + 3 * TILEB;
        #pragma unroll
        for (int ks = 0; ks < 2; ++ks) {
            const uint32_t acol = (ks * 16 + a_coff) * 2;
            const uint32_t bcol = (ks * 16 + b_coff) * 2;
            uint32_t afr[4][4], bh_[4][2], bl_[4][2];
            #pragma unroll
            for (int nt = 0; nt < 4; ++nt) {
                ldsm_x2(bh_[nt], sBh_ + (b_row + nt * 8) * 80 + bcol);
                ldsm_x2(bl_[nt], sBl_ + (b_row + nt * 8) * 80 + bcol);
            }
            #pragma unroll
            for (int mt = 0; mt < 4; ++mt)
                ldsm_x4(afr[mt], sAh_ + (a_row + mt * 16) * 80 + acol);
            #pragma unroll
            for (int mt = 0; mt < 4; ++mt)
                #pragma unroll
                for (int nt = 0; nt < 4; ++nt) {
                    mma16816(acc[mt][nt], afr[mt], bh_[nt]);
                    mma16816(acc[mt][nt], afr[mt], bl_[nt]);
                }
            #pragma unroll
            for (int mt = 0; mt < 4; ++mt)
                ldsm_x4(afr[mt], sAl_ + (a_row + mt * 16) * 80 + acol);
            #pragma unroll
            for (int mt = 0; mt < 4; ++mt)
                #pragma unroll
                for (int nt = 0; nt < 4; ++nt)
                    mma16816(acc[mt][nt], afr[mt], bh_[nt]);
        }
        __syncthreads();
    }

    const int er = lane >> 2, ec = (lane & 3) << 1;
    #pragma unroll
    for (int mt = 0; mt < 4; ++mt) {
        #pragma unroll
        for (int nt = 0; nt < 4; ++nt) {
            int gr = row0 + wm * 64 + mt * 16 + er;
            int gc = col0 + wn * 32 + nt * 8 + ec;
            const float* cc = acc[mt][nt];
            #pragma unroll
            for (int half = 0; half < 2; ++half) {
                int r = gr + half * 8;
                float2 v; v.x = cc[half * 2 + 0]; v.y = cc[half * 2 + 1];
                *(float2*)(C + (size_t)r * ldN + gc) = v;
            }
        }
    }
}

// ---------------- launch ----------------
extern "C" void kernel_launch(void* const* d_in, const int* in_sizes, int n_in,
                              void* d_out, int out_size) {
    const float* x       = (const float*)d_in[0];
    const float* w_in    = (const float*)d_in[1];
    const float* conv_w  = (const float*)d_in[2];
    const float* conv_b  = (const float*)d_in[3];
    const float* norm1_w = (const float*)d_in[4];
    const float* out_nw  = (const float*)d_in[5];
    const float* w_out   = (const float*)d_in[6];
    const float* norm2_w = (const float*)d_in[7];
    const float* ff_w1   = (const float*)d_in[8];
    const float* ff_b1   = (const float*)d_in[9];
    const float* ff_w2   = (const float*)d_in[10];
    const float* ff_b2   = (const float*)d_in[11];
    float* out = (float*)d_out;

    float *proj, *val, *par, *bcT, *scan, *x1;
    f16 *h1h, *h1l, *ygh, *h2h, *ffh;
    f16 *win, *wo, *w1, *w2, *wth, *wtl;
    cudaGetSymbolAddress((void**)&proj, g_proj);
    cudaGetSymbolAddress((void**)&val,  g_val);
    cudaGetSymbolAddress((void**)&par,  g_par);
    cudaGetSymbolAddress((void**)&bcT,  g_bcT);
    cudaGetSymbolAddress((void**)&scan, g_scan);
    cudaGetSymbolAddress((void**)&x1,   g_x1);
    cudaGetSymbolAddress((void**)&h1h,  g_h1h);  cudaGetSymbolAddress((void**)&h1l, g_h1l);
    cudaGetSymbolAddress((void**)&ygh,  g_ygh);
    cudaGetSymbolAddress((void**)&h2h,  g_h2h);
    cudaGetSymbolAddress((void**)&ffh,  g_ffh);
    cudaGetSymbolAddress((void**)&win,  g_win);
    cudaGetSymbolAddress((void**)&wo,   g_wo);
    cudaGetSymbolAddress((void**)&w1,   g_w1);
    cudaGetSymbolAddress((void**)&w2,   g_w2);
    cudaGetSymbolAddress((void**)&wth,  g_wth);
    cudaGetSymbolAddress((void**)&wtl,  g_wtl);

    cudaFuncSetAttribute(gemm_mma1, cudaFuncAttributeMaxDynamicSharedMemorySize, GEMM1_SMEM);
    cudaFuncSetAttribute(gemm_mma3, cudaFuncAttributeMaxDynamicSharedMemorySize, GEMM3_SMEM);

    // weight fp16 conversion (MLP-4 grid-stride)
    cvt16_kernel<<<(PROJ_OUT * 1024 / 4 + 1023) / 1024, 256>>>((const float4*)w_in,
        (__half2*)win, PROJ_OUT * 1024 / 4);
    cvt16_kernel<<<(1024 * 2048 / 4 + 1023) / 1024, 256>>>((const float4*)w_out,
        (__half2*)wo, 1024 * 2048 / 4);
    cvt16_kernel<<<(4096 * 1024 / 4 + 1023) / 1024, 256>>>((const float4*)ff_w1,
        (__half2*)w1, 4096 * 1024 / 4);
    cvt16_kernel<<<(1024 * 4096 / 4 + 1023) / 1024, 256>>>((const float4*)ff_w2,
        (__half2*)w2, 1024 * 4096 / 4);
    // hi/lo split of w_in tail rows (scan-parameter columns)
    split4_kernel<<<(128 * 1024 / 4 + 255) / 256, 256>>>(
        (const float4*)(w_in + (size_t)4096 * 1024), (__half2*)wth, (__half2*)wtl, 128 * 1024 / 4);

    // 1. h1 = rmsnorm(x) (fp16 hi+lo; lo used only by the 3-product tail)
    rmsnorm_split_kernel<<<BT, 256>>>(x, norm1_w, h1h, h1l);
    // 2a. proj[:, :4096] = h1 @ w_in[:4096]^T  (1-product)
    gemm_mma1<<<dim3(32, BT / 128), 256, GEMM1_SMEM>>>(h1h, win, nullptr, nullptr,
                                                       proj, nullptr, PROJ_OUT, DMODEL, 1);
    // 2b. proj[:, 4096:] = h1 @ w_in[4096:]^T  (3-product, scan params)
    gemm_mma3<<<dim3(1, BT / 128), 256, GEMM3_SMEM>>>(h1h, h1l, wth, wtl,
                                                      proj + 4096, PROJ_OUT, DMODEL);
    // 3. fused conv+silu / params / bcpack
    prep_kernel<<<BT, 256>>>(proj, conv_w, conv_b, val, par, bcT);
    // 4. scan (n-pair threads, 3 shfls)
    scan_kernel<<<2 * BQ * NHEADS, 256>>>(bcT, par, val, scan);
    // 5. yg = rmsnorm(scan * silu(gate)) (fp16 hi only)
    gated_norm_kernel<<<BT, 256>>>(proj, scan, out_nw, ygh);
    // 6. x1 = x + yg @ w_out^T  (1-product)
    gemm_mma1<<<dim3(DMODEL / 128, BT / 128), 256, GEMM1_SMEM>>>(ygh, wo, nullptr, x,
                                                    x1, nullptr, DMODEL, DINNER, 1);
    // 7. h2 = rmsnorm(x1) (fp16 hi only)
    rmsnorm_split_kernel<<<BT, 256>>>(x1, norm2_w, h2h, nullptr);
    // 8. ffh = fp16(gelu(h2 @ ff_w1^T + b1))  (1-product)
    gemm_mma1<<<dim3(DFF / 128, BT / 128), 256, GEMM1_SMEM>>>(h2h, w1, ff_b1, nullptr,
                                                 nullptr, ffh, DFF, DMODEL, 2);
    // 9. out = x1 + ffh @ ff_w2^T + b2  (1-product)
    gemm_mma1<<<dim3(DMODEL / 128, BT / 128), 256, GEMM1_SMEM>>>(ffh, w2, ff_b2, x1,
                                                    out, nullptr, DMODEL, DFF, 1);
}

// round 16
// speedup vs baseline: 1.1755x; 1.1755x over previous
#include <cuda_runtime.h>
#include <cuda_fp16.h>
#include <math.h>
#include <stdint.h>

typedef __half f16;

#define BQ 2
#define TQ 2048
#define DMODEL 1024
#define DINNER 2048
#define NHEADS 32
#define DHEAD 64
#define DCONV 4
#define PROJ_OUT 4224
#define BT 4096
#define PARAM_OFF 4096
#define BC_OFF 4160
#define DFF 4096

// ---------------- scratch (device globals; no allocation) ----------------
__device__ float g_proj[(size_t)BT * PROJ_OUT];
__device__ float g_val [(size_t)BT * DINNER];
__device__ float g_par [(size_t)BT * NHEADS * 2];
__device__ float g_bcT [(size_t)BT * 64];
__device__ float g_scan[(size_t)BT * DINNER];
__device__ float g_x1  [BT * DMODEL];
// fp16 activations
__device__ f16 g_h1h[BT * DMODEL],         g_h1l[BT * DMODEL];
__device__ f16 g_ygh[(size_t)BT * DINNER];
__device__ f16 g_h2h[BT * DMODEL];
__device__ f16 g_ffh[(size_t)BT * DFF];
// fp16 weights (hi only)
__device__ f16 g_win[PROJ_OUT * 1024];
__device__ f16 g_wo [1024 * 2048];
__device__ f16 g_w1 [4096 * 1024];
__device__ f16 g_w2 [1024 * 4096];
// fp16 hi/lo split of w_in tail rows (4096..4223) for high-precision scan params
__device__ f16 g_wth[128 * 1024], g_wtl[128 * 1024];

// ---------------- math helpers ----------------
__device__ __forceinline__ float siluf_(float x)    { return x / (1.f + __expf(-x)); }
__device__ __forceinline__ float geluf_(float x) {
    float x3 = x * x * x;
    return 0.5f * x * (1.f + tanhf(0.7978845608028654f * (x + 0.044715f * x3)));
}
__device__ __forceinline__ float sigmoidf_(float x) { return 1.f / (1.f + __expf(-x)); }
__device__ __forceinline__ float softplusf_(float x) {
    return (x > 20.f) ? x : log1pf(expf(x));
}
__device__ __forceinline__ void split1(float v, f16* h, f16* l) {
    f16 hh = __float2half_rn(v);
    *h = hh;
    *l = __float2half_rn(v - __half2float(hh));
}

__device__ __forceinline__ float block_reduce_sum(float v) {
    __shared__ float sh[32];
    int lane = threadIdx.x & 31, wid = threadIdx.x >> 5;
    int nwarps = blockDim.x >> 5;
    #pragma unroll
    for (int m = 16; m > 0; m >>= 1) v += __shfl_xor_sync(0xffffffffu, v, m);
    if (lane == 0) sh[wid] = v;
    __syncthreads();
    if (wid == 0) {
        v = (lane < nwarps) ? sh[lane] : 0.f;
        #pragma unroll
        for (int m = 16; m > 0; m >>= 1) v += __shfl_xor_sync(0xffffffffu, v, m);
        if (lane == 0) sh[0] = v;
    }
    __syncthreads();
    return sh[0];
}

// ---------------- low-level (sm_80-compatible only) ----------------
__device__ __forceinline__ uint32_t smem_u32(const void* p) {
    uint32_t a;
    asm("{ .reg .u64 t; cvta.to.shared.u64 t, %1; cvt.u32.u64 %0, t; }" : "=r"(a) : "l"(p));
    return a;
}
#define CP_ASYNC16(dst, src) \
    asm volatile("cp.async.cg.shared.global [%0], [%1], 16;" :: "r"((uint32_t)(dst)), "l"(src))
#define CP_COMMIT() asm volatile("cp.async.commit_group;" ::: "memory")

__device__ __forceinline__ void ldsm_x4(uint32_t* r, uint32_t addr) {
    asm volatile("ldmatrix.sync.aligned.m8n8.x4.shared.b16 {%0,%1,%2,%3}, [%4];"
                 : "=r"(r[0]), "=r"(r[1]), "=r"(r[2]), "=r"(r[3]) : "r"(addr));
}
__device__ __forceinline__ void ldsm_x2(uint32_t* r, uint32_t addr) {
    asm volatile("ldmatrix.sync.aligned.m8n8.x2.shared.b16 {%0,%1}, [%2];"
                 : "=r"(r[0]), "=r"(r[1]) : "r"(addr));
}
__device__ __forceinline__ void mma16816(float* c, const uint32_t* a, const uint32_t* b) {
    asm volatile("mma.sync.aligned.m16n8k16.row.col.f32.f16.f16.f32 "
                 "{%0,%1,%2,%3}, {%4,%5,%6,%7}, {%8,%9}, {%0,%1,%2,%3};"
                 : "+f"(c[0]), "+f"(c[1]), "+f"(c[2]), "+f"(c[3])
                 : "r"(a[0]), "r"(a[1]), "r"(a[2]), "r"(a[3]), "r"(b[0]), "r"(b[1]));
}

// ---------------- rmsnorm + fp16 (optional lo) (D=1024, 256 thr) ----------------
__global__ void rmsnorm_split_kernel(const float* __restrict__ x, const float* __restrict__ w,
                                     f16* __restrict__ oh, f16* __restrict__ ol) {
    int row = blockIdx.x;
    int i = threadIdx.x;
    const float4* xr = (const float4*)(x + (size_t)row * DMODEL);
    float4 v = xr[i];
    float ss = v.x * v.x + v.y * v.y + v.z * v.z + v.w * v.w;
    ss = block_reduce_sum(ss);
    float inv = rsqrtf(ss / (float)DMODEL + 1e-6f);
    float4 wv = ((const float4*)w)[i];
    float o0 = v.x * inv * wv.x, o1 = v.y * inv * wv.y;
    float o2 = v.z * inv * wv.z, o3 = v.w * inv * wv.w;
    __half2 h0, h1, l0, l1;
    split1(o0, &h0.x, &l0.x); split1(o1, &h0.y, &l0.y);
    split1(o2, &h1.x, &l1.x); split1(o3, &h1.y, &l1.y);
    __half2* ohp = (__half2*)(oh + (size_t)row * DMODEL);
    ohp[2 * i] = h0; ohp[2 * i + 1] = h1;
    if (ol) {
        __half2* olp = (__half2*)(ol + (size_t)row * DMODEL);
        olp[2 * i] = l0; olp[2 * i + 1] = l1;
    }
}

// ---------------- gated rmsnorm -> fp16 hi only (DINNER=2048) ----------------
__global__ void gated_norm_kernel(const float* __restrict__ proj, const float* __restrict__ scan_y,
                                  const float* __restrict__ w, f16* __restrict__ oh) {
    int row = blockIdx.x;
    int tid = threadIdx.x;
    const float4* prow = (const float4*)(proj + (size_t)row * PROJ_OUT);
    const float4* sy = (const float4*)(scan_y + (size_t)row * DINNER);
    float4 tv[2];
    float ss = 0.f;
    #pragma unroll
    for (int q = 0; q < 2; ++q) {
        int i = tid + q * 256;
        float4 g = prow[i];
        float4 s = sy[i];
        float4 t;
        t.x = s.x * siluf_(g.x); t.y = s.y * siluf_(g.y);
        t.z = s.z * siluf_(g.z); t.w = s.w * siluf_(g.w);
        tv[q] = t;
        ss += t.x * t.x + t.y * t.y + t.z * t.z + t.w * t.w;
    }
    ss = block_reduce_sum(ss);
    float inv = rsqrtf(ss / (float)DINNER + 1e-6f);
    __half2* ohp = (__half2*)(oh + (size_t)row * DINNER);
    #pragma unroll
    for (int q = 0; q < 2; ++q) {
        int i = tid + q * 256;
        float4 wv = ((const float4*)w)[i];
        __half2 h0, h1;
        h0.x = __float2half_rn(tv[q].x * inv * wv.x);
        h0.y = __float2half_rn(tv[q].y * inv * wv.y);
        h1.x = __float2half_rn(tv[q].z * inv * wv.z);
        h1.y = __float2half_rn(tv[q].w * inv * wv.w);
        ohp[2 * i] = h0; ohp[2 * i + 1] = h1;
    }
}

// ---------------- fp32 -> fp16 convert (vectorized) ----------------
__global__ void cvt4_kernel(const float4* __restrict__ src, __half2* __restrict__ dst, int n4) {
    int i = blockIdx.x * blockDim.x + threadIdx.x;
    if (i >= n4) return;
    float4 v = src[i];
    __half2 h0, h1;
    h0.x = __float2half_rn(v.x); h0.y = __float2half_rn(v.y);
    h1.x = __float2half_rn(v.z); h1.y = __float2half_rn(v.w);
    dst[2 * i] = h0; dst[2 * i + 1] = h1;
}

// ---------------- fp32 -> fp16 hi/lo split (vectorized) ----------------
__global__ void split4_kernel(const float4* __restrict__ src, __half2* __restrict__ hi,
                              __half2* __restrict__ lo, int n4) {
    int i = blockIdx.x * blockDim.x + threadIdx.x;
    if (i >= n4) return;
    float4 v = src[i];
    __half2 h0, h1, l0, l1;
    split1(v.x, &h0.x, &l0.x); split1(v.y, &h0.y, &l0.y);
    split1(v.z, &h1.x, &l1.x); split1(v.w, &h1.y, &l1.y);
    hi[2 * i] = h0; hi[2 * i + 1] = h1;
    lo[2 * i] = l0; lo[2 * i + 1] = l1;
}

// ---------------- fused conv+silu / params / bcpack (one block per (b,t)) ----------------
__global__ void prep_kernel(const float* __restrict__ proj, const float* __restrict__ conv_w,
                            const float* __restrict__ conv_b, float* __restrict__ value,
                            float* __restrict__ par, float* __restrict__ bcT) {
    int bt = blockIdx.x;
    int t = bt & (TQ - 1);
    int tid = threadIdx.x;
    const float* prow = proj + (size_t)bt * PROJ_OUT;
    #pragma unroll
    for (int i = 0; i < 8; ++i) {
        int c = tid + i * 256;
        float acc = conv_b[c];
        #pragma unroll
        for (int k = 0; k < DCONV; ++k) {
            int ts = t - (DCONV - 1) + k;
            if (ts >= 0)
                acc += prow[(ts - t) * (ptrdiff_t)PROJ_OUT + DINNER + c] * conv_w[c * DCONV + k];
        }
        value[(size_t)bt * DINNER + c] = siluf_(acc);
    }
    if (tid < 32) {
        int h = tid;
        par[((size_t)bt * NHEADS + h) * 2 + 0] = softplusf_(prow[PARAM_OFF + 2 * h]);
        par[((size_t)bt * NHEADS + h) * 2 + 1] = sigmoidf_(prow[PARAM_OFF + 2 * h + 1]);
    } else if (tid >= 64 && tid < 80) {
        int n = tid - 64;
        float4 v;
        v.x = prow[BC_OFF + n];
        v.y = prow[BC_OFF + 16 + n];
        v.z = prow[BC_OFF + 32 + n];
        v.w = prow[BC_OFF + 48 + n];
        ((float4*)bcT)[(size_t)bt * 16 + n] = v;
    }
}

// ---------------- sequential SSM scan (512 thr: 32 p x 16 n; pointer increments) ----------------
__global__ void scan_kernel(const float* __restrict__ bcT, const float* __restrict__ par,
                            const float* __restrict__ value, float* __restrict__ scan_y) {
    int blk = blockIdx.x;
    int bh = blk >> 1;
    int b = bh >> 5;
    int h = bh & 31;
    int half = blk & 1;
    int tid = threadIdx.x;
    int p = half * 32 + (tid >> 4);
    int n = tid & 15;
    float S0 = 0.f, S1 = 0.f;
    const size_t rowbase = (size_t)b * TQ;
    const float4* pbc = (const float4*)bcT + rowbase * 16 + n;
    const float2* pad = (const float2*)par + rowbase * NHEADS + h;
    const float*  pu  = value + rowbase * DINNER + h * DHEAD + p;
    float*        py  = scan_y + rowbase * DINNER + h * DHEAD + p;
    float4 nbc = *pbc;
    float2 nad = *pad;
    float  nu  = *pu;
    for (int t = 0; t < TQ; ++t) {
        float4 bcv = nbc; float2 ad = nad; float u = nu;
        if (t + 1 < TQ) {
            pbc += 16; pad += NHEADS; pu += DINNER;
            nbc = *pbc; nad = *pad; nu = *pu;
        }
        float A = ad.x, dt = ad.y;
        float dtA = dt * A;
        float du = dt * u;
        float s0n = fmaf(-dtA, S1, fmaf(bcv.x, du, S0));
        float s1n = fmaf(dt, S0, fmaf(1.f - dt * dtA, S1, dt * bcv.y * du));
        S0 = s0n; S1 = s1n;
        float y = bcv.z * s0n + bcv.w * s1n;
        y += __shfl_xor_sync(0xffffffffu, y, 8);
        y += __shfl_xor_sync(0xffffffffu, y, 4);
        y += __shfl_xor_sync(0xffffffffu, y, 2);
        y += __shfl_xor_sync(0xffffffffu, y, 1);
        if (n == 0) *py = y;
        py += DINNER;
    }
}

#define TILEB 10240                 // 128 rows x 80B

// ---------------- fp16 1-product GEMM: 3-stage, single sync per chunk ----------------
// mode 1: C = acc + bias? + res? (fp32) ; mode 2: Oh = fp16(gelu(acc + bias))
#define STAGEB1 (2 * TILEB)
#define GEMM1_SMEM (3 * STAGEB1)    // 61440
__global__ void __launch_bounds__(256, 2)
gemm_mma1(const f16* __restrict__ Ah, const f16* __restrict__ Bh,
          const float* __restrict__ bias, const float* __restrict__ res,
          float* __restrict__ C, f16* __restrict__ Oh,
          int N, int K, int mode) {
    extern __shared__ __align__(16) f16 dsm[];
    const uint32_t s0 = smem_u32(dsm);
    const int tid = threadIdx.x, wid = tid >> 5, lane = tid & 31;
    const int row0 = blockIdx.y * 128, col0 = blockIdx.x * 128;
    const int wm = wid & 1, wn = wid >> 1;
    const int nch = K >> 5;

    float acc[4][4][4];
    #pragma unroll
    for (int mt = 0; mt < 4; ++mt)
        #pragma unroll
        for (int nt = 0; nt < 4; ++nt)
            #pragma unroll
            for (int q = 0; q < 4; ++q) acc[mt][nt][q] = 0.f;

    const int lr = tid >> 2, lc = tid & 3;
    const f16* gAh = Ah + (size_t)(row0 + lr) * K + lc * 8;
    const f16* gBh = Bh + (size_t)(col0 + lr) * K + lc * 8;
    const uint32_t dst = lr * 80 + lc * 16;

    #define LOAD_CHUNK1(stg, k0) do {                                                  \
        uint32_t _b = s0 + (stg) * STAGEB1 + dst;                                      \
        CP_ASYNC16(_b,                   gAh + (k0));                                  \
        CP_ASYNC16(_b + 64 * 80,         gAh + (size_t)64 * K + (k0));                 \
        CP_ASYNC16(_b + TILEB,           gBh + (k0));                                  \
        CP_ASYNC16(_b + TILEB + 64 * 80, gBh + (size_t)64 * K + (k0));                 \
        CP_COMMIT();                                                                   \
    } while (0)

    LOAD_CHUNK1(0, 0);
    LOAD_CHUNK1(1, 32);

    const uint32_t a_row = (uint32_t)(wm * 64 + (lane & 15));
    const uint32_t a_coff = (uint32_t)((lane >> 4) * 8);
    const uint32_t b_row2 = (uint32_t)(wn * 32 + (lane & 7) + (((lane >> 4) & 1) << 3));
    const uint32_t b_coff = (uint32_t)(((lane >> 3) & 1) * 8);

    for (int ch = 0; ch < nch; ++ch) {
        if (ch + 1 < nch)
            asm volatile("cp.async.wait_group 1;" ::: "memory");
        else
            asm volatile("cp.async.wait_group 0;" ::: "memory");
        __syncthreads();
        if (ch + 2 < nch)
            LOAD_CHUNK1((ch + 2) % 3, (ch + 2) << 5);

        const uint32_t sb = s0 + (ch % 3) * STAGEB1;
        const uint32_t sAh_ = sb, sBh_ = sb + TILEB;
        #pragma unroll
        for (int ks = 0; ks < 2; ++ks) {
            const uint32_t acol = (ks * 16 + a_coff) * 2;
            const uint32_t bcol = (ks * 16 + b_coff) * 2;
            uint32_t afr[4][4], bfr[4][2];
            #pragma unroll
            for (int q = 0; q < 2; ++q) {
                uint32_t tmp[4];
                ldsm_x4(tmp, sBh_ + (b_row2 + q * 16) * 80 + bcol);
                bfr[2 * q][0] = tmp[0]; bfr[2 * q][1] = tmp[1];
                bfr[2 * q + 1][0] = tmp[2]; bfr[2 * q + 1][1] = tmp[3];
            }
            #pragma unroll
            for (int mt = 0; mt < 4; ++mt)
                ldsm_x4(afr[mt], sAh_ + (a_row + mt * 16) * 80 + acol);
            #pragma unroll
            for (int mt = 0; mt < 4; ++mt)
                #pragma unroll
                for (int nt = 0; nt < 4; ++nt)
                    mma16816(acc[mt][nt], afr[mt], bfr[nt]);
        }
    }

    const int er = lane >> 2, ec = (lane & 3) << 1;
    #pragma unroll
    for (int mt = 0; mt < 4; ++mt) {
        #pragma unroll
        for (int nt = 0; nt < 4; ++nt) {
            int gr = row0 + wm * 64 + mt * 16 + er;
            int gc = col0 + wn * 32 + nt * 8 + ec;
            const float* cc = acc[mt][nt];
            #pragma unroll
            for (int half = 0; half < 2; ++half) {
                int r = gr + half * 8;
                float v0 = cc[half * 2 + 0], v1 = cc[half * 2 + 1];
                if (mode == 2) {
                    v0 = geluf_(v0 + bias[gc]);
                    v1 = geluf_(v1 + bias[gc + 1]);
                    __half2 hp;
                    hp.x = __float2half_rn(v0);
                    hp.y = __float2half_rn(v1);
                    *(__half2*)(Oh + (size_t)r * N + gc) = hp;
                } else {
                    if (bias) { v0 += bias[gc]; v1 += bias[gc + 1]; }
                    if (res) {
                        const float* rp = res + (size_t)r * N + gc;
                        v0 += rp[0]; v1 += rp[1];
                    }
                    float2 v; v.x = v0; v.y = v1;
                    *(float2*)(C + (size_t)r * N + gc) = v;
                }
            }
        }
    }
}

// ---------------- fp16 3-product GEMM (high precision; in-proj tail) ----------------
#define STAGEB3 (4 * TILEB)
#define GEMM3_SMEM (2 * STAGEB3)
__global__ void __launch_bounds__(256, 2)
gemm_mma3(const f16* __restrict__ Ah, const f16* __restrict__ Al,
          const f16* __restrict__ Bh, const f16* __restrict__ Bl,
          float* __restrict__ C, int ldN, int K) {
    extern __shared__ __align__(16) f16 dsm[];
    const uint32_t s0 = smem_u32(dsm);
    const int tid = threadIdx.x, wid = tid >> 5, lane = tid & 31;
    const int row0 = blockIdx.y * 128, col0 = blockIdx.x * 128;
    const int wm = wid & 1, wn = wid >> 1;
    const int nch = K >> 5;

    float acc[4][4][4];
    #pragma unroll
    for (int mt = 0; mt < 4; ++mt)
        #pragma unroll
        for (int nt = 0; nt < 4; ++nt)
            #pragma unroll
            for (int q = 0; q < 4; ++q) acc[mt][nt][q] = 0.f;

    const int lr = tid >> 2, lc = tid & 3;
    const f16* gAh = Ah + (size_t)(row0 + lr) * K + lc * 8;
    const f16* gAl = Al + (size_t)(row0 + lr) * K + lc * 8;
    const f16* gBh = Bh + (size_t)(col0 + lr) * K + lc * 8;
    const f16* gBl = Bl + (size_t)(col0 + lr) * K + lc * 8;
    const uint32_t dst = lr * 80 + lc * 16;

    #define LOAD_CHUNK3(stg, k0) do {                                                  \
        uint32_t _b = s0 + (stg) * STAGEB3 + dst;                                      \
        CP_ASYNC16(_b,                       gAh + (k0));                              \
        CP_ASYNC16(_b + 64 * 80,             gAh + (size_t)64 * K + (k0));             \
        CP_ASYNC16(_b + TILEB,               gAl + (k0));                              \
        CP_ASYNC16(_b + TILEB + 64 * 80,     gAl + (size_t)64 * K + (k0));             \
        CP_ASYNC16(_b + 2 * TILEB,           gBh + (k0));                              \
        CP_ASYNC16(_b + 2 * TILEB + 64 * 80, gBh + (size_t)64 * K + (k0));             \
        CP_ASYNC16(_b + 3 * TILEB,           gBl + (k0));                              \
        CP_ASYNC16(_b + 3 * TILEB + 64 * 80, gBl + (size_t)64 * K + (k0));             \
        CP_COMMIT();                                                                   \
    } while (0)

    LOAD_CHUNK3(0, 0);

    const uint32_t a_row = (uint32_t)(wm * 64 + (lane & 15));
    const uint32_t a_coff = (uint32_t)((lane >> 4) * 8);
    const uint32_t b_row = (uint32_t)(wn * 32 + (lane & 7));
    const uint32_t b_coff = (uint32_t)(((lane >> 3) & 1) * 8);

    for (int ch = 0; ch < nch; ++ch) {
        const int stg = ch & 1;
        if (ch + 1 < nch) {
            LOAD_CHUNK3(stg ^ 1, (ch + 1) << 5);
            asm volatile("cp.async.wait_group 1;" ::: "memory");
        } else {
            asm volatile("cp.async.wait_group 0;" ::: "memory");
        }
        __syncthreads();

        const uint32_t sb = s0 + stg * STAGEB3;
        const uint32_t sAh_ = sb, sAl_ = sb + TILEB, sBh_ = sb + 2 * TILEB, sBl_ = sb + 3 * TILEB;
        #pragma unroll
        for (int ks = 0; ks < 2; ++ks) {
            const uint32_t acol = (ks * 16 + a_coff) * 2;
            const uint32_t bcol = (ks * 16 + b_coff) * 2;
            uint32_t afr[4][4], bh_[4][2], bl_[4][2];
            #pragma unroll
            for (int nt = 0; nt < 4; ++nt) {
                ldsm_x2(bh_[nt], sBh_ + (b_row + nt * 8) * 80 + bcol);
                ldsm_x2(bl_[nt], sBl_ + (b_row + nt * 8) * 80 + bcol);
            }
            #pragma unroll
            for (int mt = 0; mt < 4; ++mt)
                ldsm_x4(afr[mt], sAh_ + (a_row + mt * 16) * 80 + acol);
            #pragma unroll
            for (int mt = 0; mt < 4; ++mt)
                #pragma unroll
                for (int nt = 0; nt < 4; ++nt) {
                    mma16816(acc[mt][nt], afr[mt], bh_[nt]);
                    mma16816(acc[mt][nt], afr[mt], bl_[nt]);
                }
            #pragma unroll
            for (int mt = 0; mt < 4; ++mt)
                ldsm_x4(afr[mt], sAl_ + (a_row + mt * 16) * 80 + acol);
            #pragma unroll
            for (int mt = 0; mt < 4; ++mt)
                #pragma unroll
                for (int nt = 0; nt < 4; ++nt)
                    mma16816(acc[mt][nt], afr[mt], bh_[nt]);
        }
        __syncthreads();
    }

    const int er = lane >> 2, ec = (lane & 3) << 1;
    #pragma unroll
    for (int mt = 0; mt < 4; ++mt) {
        #pragma unroll
        for (int nt = 0; nt < 4; ++nt) {
            int gr = row0 + wm * 64 + mt * 16 + er;
            int gc = col0 + wn * 32 + nt * 8 + ec;
            const float* cc = acc[mt][nt];
            #pragma unroll
            for (int half = 0; half < 2; ++half) {
                int r = gr + half * 8;
                float2 v; v.x = cc[half * 2 + 0]; v.y = cc[half * 2 + 1];
                *(float2*)(C + (size_t)r * ldN + gc) = v;
            }
        }
    }
}

// ---------------- launch ----------------
extern "C" void kernel_launch(void* const* d_in, const int* in_sizes, int n_in,
                              void* d_out, int out_size) {
    const float* x       = (const float*)d_in[0];
    const float* w_in    = (const float*)d_in[1];
    const float* conv_w  = (const float*)d_in[2];
    const float* conv_b  = (const float*)d_in[3];
    const float* norm1_w = (const float*)d_in[4];
    const float* out_nw  = (const float*)d_in[5];
    const float* w_out   = (const float*)d_in[6];
    const float* norm2_w = (const float*)d_in[7];
    const float* ff_w1   = (const float*)d_in[8];
    const float* ff_b1   = (const float*)d_in[9];
    const float* ff_w2   = (const float*)d_in[10];
    const float* ff_b2   = (const float*)d_in[11];
    float* out = (float*)d_out;

    float *proj, *val, *par, *bcT, *scan, *x1;
    f16 *h1h, *h1l, *ygh, *h2h, *ffh;
    f16 *win, *wo, *w1, *w2, *wth, *wtl;
    cudaGetSymbolAddress((void**)&proj, g_proj);
    cudaGetSymbolAddress((void**)&val,  g_val);
    cudaGetSymbolAddress((void**)&par,  g_par);
    cudaGetSymbolAddress((void**)&bcT,  g_bcT);
    cudaGetSymbolAddress((void**)&scan, g_scan);
    cudaGetSymbolAddress((void**)&x1,   g_x1);
    cudaGetSymbolAddress((void**)&h1h,  g_h1h);  cudaGetSymbolAddress((void**)&h1l, g_h1l);
    cudaGetSymbolAddress((void**)&ygh,  g_ygh);
    cudaGetSymbolAddress((void**)&h2h,  g_h2h);
    cudaGetSymbolAddress((void**)&ffh,  g_ffh);
    cudaGetSymbolAddress((void**)&win,  g_win);
    cudaGetSymbolAddress((void**)&wo,   g_wo);
    cudaGetSymbolAddress((void**)&w1,   g_w1);
    cudaGetSymbolAddress((void**)&w2,   g_w2);
    cudaGetSymbolAddress((void**)&wth,  g_wth);
    cudaGetSymbolAddress((void**)&wtl,  g_wtl);

    cudaFuncSetAttribute(gemm_mma1, cudaFuncAttributeMaxDynamicSharedMemorySize, GEMM1_SMEM);
    cudaFuncSetAttribute(gemm_mma3, cudaFuncAttributeMaxDynamicSharedMemorySize, GEMM3_SMEM);

    // weight fp16 conversion (idempotent)
    cvt4_kernel<<<(PROJ_OUT * 1024 / 4 + 255) / 256, 256>>>((const float4*)w_in,
        (__half2*)win, PROJ_OUT * 1024 / 4);
    cvt4_kernel<<<(1024 * 2048 / 4 + 255) / 256, 256>>>((const float4*)w_out,
        (__half2*)wo, 1024 * 2048 / 4);
    cvt4_kernel<<<(4096 * 1024 / 4 + 255) / 256, 256>>>((const float4*)ff_w1,
        (__half2*)w1, 4096 * 1024 / 4);
    cvt4_kernel<<<(1024 * 4096 / 4 + 255) / 256, 256>>>((const float4*)ff_w2,
        (__half2*)w2, 1024 * 4096 / 4);
    // hi/lo split of w_in tail rows (scan-parameter columns)
    split4_kernel<<<(128 * 1024 / 4 + 255) / 256, 256>>>(
        (const float4*)(w_in + (size_t)4096 * 1024), (__half2*)wth, (__half2*)wtl, 128 * 1024 / 4);

    // 1. h1 = rmsnorm(x) (fp16 hi+lo; lo used only by the 3-product tail)
    rmsnorm_split_kernel<<<BT, 256>>>(x, norm1_w, h1h, h1l);
    // 2a. proj[:, :4096] = h1 @ w_in[:4096]^T  (1-product)
    gemm_mma1<<<dim3(32, BT / 128), 256, GEMM1_SMEM>>>(h1h, win, nullptr, nullptr,
                                                       proj, nullptr, PROJ_OUT, DMODEL, 1);
    // 2b. proj[:, 4096:] = h1 @ w_in[4096:]^T  (3-product, scan params)
    gemm_mma3<<<dim3(1, BT / 128), 256, GEMM3_SMEM>>>(h1h, h1l, wth, wtl,
                                                      proj + 4096, PROJ_OUT, DMODEL);
    // 3. fused conv+silu / params / bcpack
    prep_kernel<<<BT, 256>>>(proj, conv_w, conv_b, val, par, bcT);
    // 4. scan (512 thr, pointer increments)
    scan_kernel<<<2 * BQ * NHEADS, 512>>>(bcT, par, val, scan);
    // 5. yg = rmsnorm(scan * silu(gate)) (fp16 hi only)
    gated_norm_kernel<<<BT, 256>>>(proj, scan, out_nw, ygh);
    // 6. x1 = x + yg @ w_out^T  (1-product)
    gemm_mma1<<<dim3(DMODEL / 128, BT / 128), 256, GEMM1_SMEM>>>(ygh, wo, nullptr, x,
                                                    x1, nullptr, DMODEL, DINNER, 1);
    // 7. h2 = rmsnorm(x1) (fp16 hi only)
    rmsnorm_split_kernel<<<BT, 256>>>(x1, norm2_w, h2h, nullptr);
    // 8. ffh = fp16(gelu(h2 @ ff_w1^T + b1))  (1-product)
    gemm_mma1<<<dim3(DFF / 128, BT / 128), 256, GEMM1_SMEM>>>(h2h, w1, ff_b1, nullptr,
                                                 nullptr, ffh, DFF, DMODEL, 2);
    // 9. out = x1 + ffh @ ff_w2^T + b2  (1-product)
    gemm_mma1<<<dim3(DMODEL / 128, BT / 128), 256, GEMM1_SMEM>>>(ffh, w2, ff_b2, x1,
                                                    out, nullptr, DMODEL, DFF, 1);
}

// round 17
// speedup vs baseline: 1.2365x; 1.0519x over previous
#include <cuda_runtime.h>
#include <cuda_fp16.h>
#include <math.h>
#include <stdint.h>

typedef __half f16;

#define BQ 2
#define TQ 2048
#define DMODEL 1024
#define DINNER 2048
#define NHEADS 32
#define DHEAD 64
#define DCONV 4
#define PROJ_OUT 4224
#define BT 4096
#define PARAM_OFF 4096
#define BC_OFF 4160
#define DFF 4096

// ---------------- scratch (device globals; no allocation) ----------------
__device__ float g_proj[(size_t)BT * PROJ_OUT];
__device__ float g_val [(size_t)BT * DINNER];
__device__ float g_par [(size_t)BT * NHEADS * 2];
__device__ float g_bcT [(size_t)BT * 64];
__device__ float g_scan[(size_t)BT * DINNER];
__device__ float g_x1  [BT * DMODEL];
// fp16 activations
__device__ f16 g_h1h[BT * DMODEL],         g_h1l[BT * DMODEL];
__device__ f16 g_ygh[(size_t)BT * DINNER];
__device__ f16 g_h2h[BT * DMODEL];
__device__ f16 g_ffh[(size_t)BT * DFF];
// fp16 weights (hi only)
__device__ f16 g_win[PROJ_OUT * 1024];
__device__ f16 g_wo [1024 * 2048];
__device__ f16 g_w1 [4096 * 1024];
__device__ f16 g_w2 [1024 * 4096];
// fp16 hi/lo split of w_in tail rows (4096..4223) for high-precision scan params
__device__ f16 g_wth[128 * 1024], g_wtl[128 * 1024];

// ---------------- math helpers ----------------
__device__ __forceinline__ float siluf_(float x)    { return x / (1.f + __expf(-x)); }
__device__ __forceinline__ float geluf_(float x) {
    float x3 = x * x * x;
    return 0.5f * x * (1.f + tanhf(0.7978845608028654f * (x + 0.044715f * x3)));
}
__device__ __forceinline__ float sigmoidf_(float x) { return 1.f / (1.f + __expf(-x)); }
__device__ __forceinline__ float softplusf_(float x) {
    return (x > 20.f) ? x : log1pf(expf(x));
}
__device__ __forceinline__ void split1(float v, f16* h, f16* l) {
    f16 hh = __float2half_rn(v);
    *h = hh;
    *l = __float2half_rn(v - __half2float(hh));
}

__device__ __forceinline__ float block_reduce_sum(float v) {
    __shared__ float sh[32];
    int lane = threadIdx.x & 31, wid = threadIdx.x >> 5;
    int nwarps = blockDim.x >> 5;
    #pragma unroll
    for (int m = 16; m > 0; m >>= 1) v += __shfl_xor_sync(0xffffffffu, v, m);
    if (lane == 0) sh[wid] = v;
    __syncthreads();
    if (wid == 0) {
        v = (lane < nwarps) ? sh[lane] : 0.f;
        #pragma unroll
        for (int m = 16; m > 0; m >>= 1) v += __shfl_xor_sync(0xffffffffu, v, m);
        if (lane == 0) sh[0] = v;
    }
    __syncthreads();
    return sh[0];
}

// ---------------- low-level (sm_80-compatible only) ----------------
__device__ __forceinline__ uint32_t smem_u32(const void* p) {
    uint32_t a;
    asm("{ .reg .u64 t; cvta.to.shared.u64 t, %1; cvt.u32.u64 %0, t; }" : "=r"(a) : "l"(p));
    return a;
}
#define CP_ASYNC16(dst, src) \
    asm volatile("cp.async.cg.shared.global [%0], [%1], 16;" :: "r"((uint32_t)(dst)), "l"(src))
#define CP_COMMIT() asm volatile("cp.async.commit_group;" ::: "memory")

__device__ __forceinline__ void ldsm_x4(uint32_t* r, uint32_t addr) {
    asm volatile("ldmatrix.sync.aligned.m8n8.x4.shared.b16 {%0,%1,%2,%3}, [%4];"
                 : "=r"(r[0]), "=r"(r[1]), "=r"(r[2]), "=r"(r[3]) : "r"(addr));
}
__device__ __forceinline__ void ldsm_x2(uint32_t* r, uint32_t addr) {
    asm volatile("ldmatrix.sync.aligned.m8n8.x2.shared.b16 {%0,%1}, [%2];"
                 : "=r"(r[0]), "=r"(r[1]) : "r"(addr));
}
__device__ __forceinline__ void mma16816(float* c, const uint32_t* a, const uint32_t* b) {
    asm volatile("mma.sync.aligned.m16n8k16.row.col.f32.f16.f16.f32 "
                 "{%0,%1,%2,%3}, {%4,%5,%6,%7}, {%8,%9}, {%0,%1,%2,%3};"
                 : "+f"(c[0]), "+f"(c[1]), "+f"(c[2]), "+f"(c[3])
                 : "r"(a[0]), "r"(a[1]), "r"(a[2]), "r"(a[3]), "r"(b[0]), "r"(b[1]));
}

// ---------------- rmsnorm + fp16 (optional lo) (D=1024, 256 thr) ----------------
__global__ void rmsnorm_split_kernel(const float* __restrict__ x, const float* __restrict__ w,
                                     f16* __restrict__ oh, f16* __restrict__ ol) {
    int row = blockIdx.x;
    int i = threadIdx.x;
    const float4* xr = (const float4*)(x + (size_t)row * DMODEL);
    float4 v = xr[i];
    float ss = v.x * v.x + v.y * v.y + v.z * v.z + v.w * v.w;
    ss = block_reduce_sum(ss);
    float inv = rsqrtf(ss / (float)DMODEL + 1e-6f);
    float4 wv = ((const float4*)w)[i];
    float o0 = v.x * inv * wv.x, o1 = v.y * inv * wv.y;
    float o2 = v.z * inv * wv.z, o3 = v.w * inv * wv.w;
    __half2 h0, h1, l0, l1;
    split1(o0, &h0.x, &l0.x); split1(o1, &h0.y, &l0.y);
    split1(o2, &h1.x, &l1.x); split1(o3, &h1.y, &l1.y);
    __half2* ohp = (__half2*)(oh + (size_t)row * DMODEL);
    ohp[2 * i] = h0; ohp[2 * i + 1] = h1;
    if (ol) {
        __half2* olp = (__half2*)(ol + (size_t)row * DMODEL);
        olp[2 * i] = l0; olp[2 * i + 1] = l1;
    }
}

// ---------------- gated rmsnorm -> fp16 hi only (DINNER=2048) ----------------
__global__ void gated_norm_kernel(const float* __restrict__ proj, const float* __restrict__ scan_y,
                                  const float* __restrict__ w, f16* __restrict__ oh) {
    int row = blockIdx.x;
    int tid = threadIdx.x;
    const float4* prow = (const float4*)(proj + (size_t)row * PROJ_OUT);
    const float4* sy = (const float4*)(scan_y + (size_t)row * DINNER);
    float4 tv[2];
    float ss = 0.f;
    #pragma unroll
    for (int q = 0; q < 2; ++q) {
        int i = tid + q * 256;
        float4 g = prow[i];
        float4 s = sy[i];
        float4 t;
        t.x = s.x * siluf_(g.x); t.y = s.y * siluf_(g.y);
        t.z = s.z * siluf_(g.z); t.w = s.w * siluf_(g.w);
        tv[q] = t;
        ss += t.x * t.x + t.y * t.y + t.z * t.z + t.w * t.w;
    }
    ss = block_reduce_sum(ss);
    float inv = rsqrtf(ss / (float)DINNER + 1e-6f);
    __half2* ohp = (__half2*)(oh + (size_t)row * DINNER);
    #pragma unroll
    for (int q = 0; q < 2; ++q) {
        int i = tid + q * 256;
        float4 wv = ((const float4*)w)[i];
        __half2 h0, h1;
        h0.x = __float2half_rn(tv[q].x * inv * wv.x);
        h0.y = __float2half_rn(tv[q].y * inv * wv.y);
        h1.x = __float2half_rn(tv[q].z * inv * wv.z);
        h1.y = __float2half_rn(tv[q].w * inv * wv.w);
        ohp[2 * i] = h0; ohp[2 * i + 1] = h1;
    }
}

// ---------------- fp32 -> fp16 convert (vectorized) ----------------
__global__ void cvt4_kernel(const float4* __restrict__ src, __half2* __restrict__ dst, int n4) {
    int i = blockIdx.x * blockDim.x + threadIdx.x;
    if (i >= n4) return;
    float4 v = src[i];
    __half2 h0, h1;
    h0.x = __float2half_rn(v.x); h0.y = __float2half_rn(v.y);
    h1.x = __float2half_rn(v.z); h1.y = __float2half_rn(v.w);
    dst[2 * i] = h0; dst[2 * i + 1] = h1;
}

// ---------------- fp32 -> fp16 hi/lo split (vectorized) ----------------
__global__ void split4_kernel(const float4* __restrict__ src, __half2* __restrict__ hi,
                              __half2* __restrict__ lo, int n4) {
    int i = blockIdx.x * blockDim.x + threadIdx.x;
    if (i >= n4) return;
    float4 v = src[i];
    __half2 h0, h1, l0, l1;
    split1(v.x, &h0.x, &l0.x); split1(v.y, &h0.y, &l0.y);
    split1(v.z, &h1.x, &l1.x); split1(v.w, &h1.y, &l1.y);
    hi[2 * i] = h0; hi[2 * i + 1] = h1;
    lo[2 * i] = l0; lo[2 * i + 1] = l1;
}

// ---------------- fused conv+silu / params / bcpack (one block per (b,t)) ----------------
// conv vectorized: thread handles 2 float4 channel groups (8 channels)
__global__ void prep_kernel(const float* __restrict__ proj, const float* __restrict__ conv_w,
                            const float* __restrict__ conv_b, float* __restrict__ value,
                            float* __restrict__ par, float* __restrict__ bcT) {
    int bt = blockIdx.x;
    int t = bt & (TQ - 1);
    int tid = threadIdx.x;
    const float* prow = proj + (size_t)bt * PROJ_OUT;
    float4* vout = (float4*)(value + (size_t)bt * DINNER);
    #pragma unroll
    for (int i = 0; i < 2; ++i) {
        int c4 = tid + i * 256;          // float4 channel-group index (0..511)
        int c = c4 << 2;
        float4 acc = ((const float4*)conv_b)[c4];
        float4 w0 = ((const float4*)conv_w)[c + 0];
        float4 w1 = ((const float4*)conv_w)[c + 1];
        float4 w2 = ((const float4*)conv_w)[c + 2];
        float4 w3 = ((const float4*)conv_w)[c + 3];
        #pragma unroll
        for (int k = 0; k < DCONV; ++k) {
            int ts = t - (DCONV - 1) + k;
            if (ts >= 0) {
                float4 v = *(const float4*)(prow + (ptrdiff_t)(ts - t) * PROJ_OUT + DINNER + c);
                acc.x = fmaf(v.x, ((const float*)&w0)[k], acc.x);
                acc.y = fmaf(v.y, ((const float*)&w1)[k], acc.y);
                acc.z = fmaf(v.z, ((const float*)&w2)[k], acc.z);
                acc.w = fmaf(v.w, ((const float*)&w3)[k], acc.w);
            }
        }
        float4 o;
        o.x = siluf_(acc.x); o.y = siluf_(acc.y);
        o.z = siluf_(acc.z); o.w = siluf_(acc.w);
        vout[c4] = o;
    }
    if (tid < 32) {
        int h = tid;
        par[((size_t)bt * NHEADS + h) * 2 + 0] = softplusf_(prow[PARAM_OFF + 2 * h]);
        par[((size_t)bt * NHEADS + h) * 2 + 1] = sigmoidf_(prow[PARAM_OFF + 2 * h + 1]);
    } else if (tid >= 64 && tid < 80) {
        int n = tid - 64;
        float4 v;
        v.x = prow[BC_OFF + n];
        v.y = prow[BC_OFF + 16 + n];
        v.z = prow[BC_OFF + 32 + n];
        v.w = prow[BC_OFF + 48 + n];
        ((float4*)bcT)[(size_t)bt * 16 + n] = v;
    }
}

// ---------------- sequential SSM scan (R14 exact: 512 thr, index addressing) ----------------
__global__ void scan_kernel(const float* __restrict__ bcT, const float* __restrict__ par,
                            const float* __restrict__ value, float* __restrict__ scan_y) {
    int blk = blockIdx.x;
    int bh = blk >> 1;
    int b = bh >> 5;
    int h = bh & 31;
    int half = blk & 1;
    int tid = threadIdx.x;
    int p = half * 32 + (tid >> 4);
    int n = tid & 15;
    float S0 = 0.f, S1 = 0.f;
    const size_t rowbase = (size_t)b * TQ;
    const float4* bc4 = (const float4*)bcT;
    const float2* ad2 = (const float2*)par;
    float4 nbc = bc4[rowbase * 16 + n];
    float2 nad = ad2[rowbase * NHEADS + h];
    float  nu  = value[rowbase * DINNER + h * DHEAD + p];
    for (int t = 0; t < TQ; ++t) {
        float4 bcv = nbc; float2 ad = nad; float u = nu;
        if (t + 1 < TQ) {
            size_t r2 = rowbase + t + 1;
            nbc = bc4[r2 * 16 + n];
            nad = ad2[r2 * NHEADS + h];
            nu  = value[r2 * DINNER + h * DHEAD + p];
        }
        float A = ad.x, dt = ad.y;
        float dtA = dt * A;
        float du = dt * u;
        float s0n = fmaf(-dtA, S1, fmaf(bcv.x, du, S0));
        float s1n = fmaf(dt, S0, fmaf(1.f - dt * dtA, S1, dt * bcv.y * du));
        S0 = s0n; S1 = s1n;
        float y = bcv.z * s0n + bcv.w * s1n;
        y += __shfl_xor_sync(0xffffffffu, y, 8);
        y += __shfl_xor_sync(0xffffffffu, y, 4);
        y += __shfl_xor_sync(0xffffffffu, y, 2);
        y += __shfl_xor_sync(0xffffffffu, y, 1);
        if (n == 0) scan_y[(rowbase + t) * DINNER + h * DHEAD + p] = y;
    }
}

#define TILEB 10240                 // 128 rows x 80B

// ---------------- fp16 1-product GEMM: 3-stage, single sync per chunk ----------------
// mode 1: C = acc + bias? + res? (fp32) ; mode 2: Oh = fp16(gelu(acc + bias))
#define STAGEB1 (2 * TILEB)
#define GEMM1_SMEM (3 * STAGEB1)    // 61440
__global__ void __launch_bounds__(256, 2)
gemm_mma1(const f16* __restrict__ Ah, const f16* __restrict__ Bh,
          const float* __restrict__ bias, const float* __restrict__ res,
          float* __restrict__ C, f16* __restrict__ Oh,
          int N, int K, int mode) {
    extern __shared__ __align__(16) f16 dsm[];
    const uint32_t s0 = smem_u32(dsm);
    const int tid = threadIdx.x, wid = tid >> 5, lane = tid & 31;
    const int row0 = blockIdx.y * 128, col0 = blockIdx.x * 128;
    const int wm = wid & 1, wn = wid >> 1;
    const int nch = K >> 5;

    float acc[4][4][4];
    #pragma unroll
    for (int mt = 0; mt < 4; ++mt)
        #pragma unroll
        for (int nt = 0; nt < 4; ++nt)
            #pragma unroll
            for (int q = 0; q < 4; ++q) acc[mt][nt][q] = 0.f;

    const int lr = tid >> 2, lc = tid & 3;
    const f16* gAh = Ah + (size_t)(row0 + lr) * K + lc * 8;
    const f16* gBh = Bh + (size_t)(col0 + lr) * K + lc * 8;
    const uint32_t dst = lr * 80 + lc * 16;

    #define LOAD_CHUNK1(stg, k0) do {                                                  \
        uint32_t _b = s0 + (stg) * STAGEB1 + dst;                                      \
        CP_ASYNC16(_b,                   gAh + (k0));                                  \
        CP_ASYNC16(_b + 64 * 80,         gAh + (size_t)64 * K + (k0));                 \
        CP_ASYNC16(_b + TILEB,           gBh + (k0));                                  \
        CP_ASYNC16(_b + TILEB + 64 * 80, gBh + (size_t)64 * K + (k0));                 \
        CP_COMMIT();                                                                   \
    } while (0)

    LOAD_CHUNK1(0, 0);
    LOAD_CHUNK1(1, 32);

    const uint32_t a_row = (uint32_t)(wm * 64 + (lane & 15));
    const uint32_t a_coff = (uint32_t)((lane >> 4) * 8);
    const uint32_t b_row2 = (uint32_t)(wn * 32 + (lane & 7) + (((lane >> 4) & 1) << 3));
    const uint32_t b_coff = (uint32_t)(((lane >> 3) & 1) * 8);

    for (int ch = 0; ch < nch; ++ch) {
        if (ch + 1 < nch)
            asm volatile("cp.async.wait_group 1;" ::: "memory");
        else
            asm volatile("cp.async.wait_group 0;" ::: "memory");
        __syncthreads();
        if (ch + 2 < nch)
            LOAD_CHUNK1((ch + 2) % 3, (ch + 2) << 5);

        const uint32_t sb = s0 + (ch % 3) * STAGEB1;
        const uint32_t sAh_ = sb, sBh_ = sb + TILEB;
        #pragma unroll
        for (int ks = 0; ks < 2; ++ks) {
            const uint32_t acol = (ks * 16 + a_coff) * 2;
            const uint32_t bcol = (ks * 16 + b_coff) * 2;
            uint32_t afr[4][4], bfr[4][2];
            #pragma unroll
            for (int q = 0; q < 2; ++q) {
                uint32_t tmp[4];
                ldsm_x4(tmp, sBh_ + (b_row2 + q * 16) * 80 + bcol);
                bfr[2 * q][0] = tmp[0]; bfr[2 * q][1] = tmp[1];
                bfr[2 * q + 1][0] = tmp[2]; bfr[2 * q + 1][1] = tmp[3];
            }
            #pragma unroll
            for (int mt = 0; mt < 4; ++mt)
                ldsm_x4(afr[mt], sAh_ + (a_row + mt * 16) * 80 + acol);
            #pragma unroll
            for (int mt = 0; mt < 4; ++mt)
                #pragma unroll
                for (int nt = 0; nt < 4; ++nt)
                    mma16816(acc[mt][nt], afr[mt], bfr[nt]);
        }
    }

    const int er = lane >> 2, ec = (lane & 3) << 1;
    #pragma unroll
    for (int mt = 0; mt < 4; ++mt) {
        #pragma unroll
        for (int nt = 0; nt < 4; ++nt) {
            int gr = row0 + wm * 64 + mt * 16 + er;
            int gc = col0 + wn * 32 + nt * 8 + ec;
            const float* cc = acc[mt][nt];
            #pragma unroll
            for (int half = 0; half < 2; ++half) {
                int r = gr + half * 8;
                float v0 = cc[half * 2 + 0], v1 = cc[half * 2 + 1];
                if (mode == 2) {
                    v0 = geluf_(v0 + bias[gc]);
                    v1 = geluf_(v1 + bias[gc + 1]);
                    __half2 hp;
                    hp.x = __float2half_rn(v0);
                    hp.y = __float2half_rn(v1);
                    *(__half2*)(Oh + (size_t)r * N + gc) = hp;
                } else {
                    if (bias) { v0 += bias[gc]; v1 += bias[gc + 1]; }
                    if (res) {
                        const float* rp = res + (size_t)r * N + gc;
                        v0 += rp[0]; v1 += rp[1];
                    }
                    float2 v; v.x = v0; v.y = v1;
                    *(float2*)(C + (size_t)r * N + gc) = v;
                }
            }
        }
    }
}

// ---------------- fp16 3-product GEMM (high precision; in-proj tail) ----------------
#define STAGEB3 (4 * TILEB)
#define GEMM3_SMEM (2 * STAGEB3)
__global__ void __launch_bounds__(256, 2)
gemm_mma3(const f16* __restrict__ Ah, const f16* __restrict__ Al,
          const f16* __restrict__ Bh, const f16* __restrict__ Bl,
          float* __restrict__ C, int ldN, int K) {
    extern __shared__ __align__(16) f16 dsm[];
    const uint32_t s0 = smem_u32(dsm);
    const int tid = threadIdx.x, wid = tid >> 5, lane = tid & 31;
    const int row0 = blockIdx.y * 128, col0 = blockIdx.x * 128;
    const int wm = wid & 1, wn = wid >> 1;
    const int nch = K >> 5;

    float acc[4][4][4];
    #pragma unroll
    for (int mt = 0; mt < 4; ++mt)
        #pragma unroll
        for (int nt = 0; nt < 4; ++nt)
            #pragma unroll
            for (int q = 0; q < 4; ++q) acc[mt][nt][q] = 0.f;

    const int lr = tid >> 2, lc = tid & 3;
    const f16* gAh = Ah + (size_t)(row0 + lr) * K + lc * 8;
    const f16* gAl = Al + (size_t)(row0 + lr) * K + lc * 8;
    const f16* gBh = Bh + (size_t)(col0 + lr) * K + lc * 8;
    const f16* gBl = Bl + (size_t)(col0 + lr) * K + lc * 8;
    const uint32_t dst = lr * 80 + lc * 16;

    #define LOAD_CHUNK3(stg, k0) do {                                                  \
        uint32_t _b = s0 + (stg) * STAGEB3 + dst;                                      \
        CP_ASYNC16(_b,                       gAh + (k0));                              \
        CP_ASYNC16(_b + 64 * 80,             gAh + (size_t)64 * K + (k0));             \
        CP_ASYNC16(_b + TILEB,               gAl + (k0));                              \
        CP_ASYNC16(_b + TILEB + 64 * 80,     gAl + (size_t)64 * K + (k0));             \
        CP_ASYNC16(_b + 2 * TILEB,           gBh + (k0));                              \
        CP_ASYNC16(_b + 2 * TILEB + 64 * 80, gBh + (size_t)64 * K + (k0));             \
        CP_ASYNC16(_b + 3 * TILEB,           gBl + (k0));                              \
        CP_ASYNC16(_b + 3 * TILEB + 64 * 80, gBl + (size_t)64 * K + (k0));             \
        CP_COMMIT();                                                                   \
    } while (0)

    LOAD_CHUNK3(0, 0);

    const uint32_t a_row = (uint32_t)(wm * 64 + (lane & 15));
    const uint32_t a_coff = (uint32_t)((lane >> 4) * 8);
    const uint32_t b_row = (uint32_t)(wn * 32 + (lane & 7));
    const uint32_t b_coff = (uint32_t)(((lane >> 3) & 1) * 8);

    for (int ch = 0; ch < nch; ++ch) {
        const int stg = ch & 1;
        if (ch + 1 < nch) {
            LOAD_CHUNK3(stg ^ 1, (ch + 1) << 5);
            asm volatile("cp.async.wait_group 1;" ::: "memory");
        } else {
            asm volatile("cp.async.wait_group 0;" ::: "memory");
        }
        __syncthreads();

        const uint32_t sb = s0 + stg * STAGEB3;
        const uint32_t sAh_ = sb, sAl_ = sb + TILEB, sBh_ = sb + 2 * TILEB, sBl_ = sb + 3 * TILEB;
        #pragma unroll
        for (int ks = 0; ks < 2; ++ks) {
            const uint32_t acol = (ks * 16 + a_coff) * 2;
            const uint32_t bcol = (ks * 16 + b_coff) * 2;
            uint32_t afr[4][4], bh_[4][2], bl_[4][2];
            #pragma unroll
            for (int nt = 0; nt < 4; ++nt) {
                ldsm_x2(bh_[nt], sBh_ + (b_row + nt * 8) * 80 + bcol);
                ldsm_x2(bl_[nt], sBl_ + (b_row + nt * 8) * 80 + bcol);
            }
            #pragma unroll
            for (int mt = 0; mt < 4; ++mt)
                ldsm_x4(afr[mt], sAh_ + (a_row + mt * 16) * 80 + acol);
            #pragma unroll
            for (int mt = 0; mt < 4; ++mt)
                #pragma unroll
                for (int nt = 0; nt < 4; ++nt) {
                    mma16816(acc[mt][nt], afr[mt], bh_[nt]);
                    mma16816(acc[mt][nt], afr[mt], bl_[nt]);
                }
            #pragma unroll
            for (int mt = 0; mt < 4; ++mt)
                ldsm_x4(afr[mt], sAl_ + (a_row + mt * 16) * 80 + acol);
            #pragma unroll
            for (int mt = 0; mt < 4; ++mt)
                #pragma unroll
                for (int nt = 0; nt < 4; ++nt)
                    mma16816(acc[mt][nt], afr[mt], bh_[nt]);
        }
        __syncthreads();
    }

    const int er = lane >> 2, ec = (lane & 3) << 1;
    #pragma unroll
    for (int mt = 0; mt < 4; ++mt) {
        #pragma unroll
        for (int nt = 0; nt < 4; ++nt) {
            int gr = row0 + wm * 64 + mt * 16 + er;
            int gc = col0 + wn * 32 + nt * 8 + ec;
            const float* cc = acc[mt][nt];
            #pragma unroll
            for (int half = 0; half < 2; ++half) {
                int r = gr + half * 8;
                float2 v; v.x = cc[half * 2 + 0]; v.y = cc[half * 2 + 1];
                *(float2*)(C + (size_t)r * ldN + gc) = v;
            }
        }
    }
}

// ---------------- launch ----------------
extern "C" void kernel_launch(void* const* d_in, const int* in_sizes, int n_in,
                              void* d_out, int out_size) {
    const float* x       = (const float*)d_in[0];
    const float* w_in    = (const float*)d_in[1];
    const float* conv_w  = (const float*)d_in[2];
    const float* conv_b  = (const float*)d_in[3];
    const float* norm1_w = (const float*)d_in[4];
    const float* out_nw  = (const float*)d_in[5];
    const float* w_out   = (const float*)d_in[6];
    const float* norm2_w = (const float*)d_in[7];
    const float* ff_w1   = (const float*)d_in[8];
    const float* ff_b1   = (const float*)d_in[9];
    const float* ff_w2   = (const float*)d_in[10];
    const float* ff_b2   = (const float*)d_in[11];
    float* out = (float*)d_out;

    float *proj, *val, *par, *bcT, *scan, *x1;
    f16 *h1h, *h1l, *ygh, *h2h, *ffh;
    f16 *win, *wo, *w1, *w2, *wth, *wtl;
    cudaGetSymbolAddress((void**)&proj, g_proj);
    cudaGetSymbolAddress((void**)&val,  g_val);
    cudaGetSymbolAddress((void**)&par,  g_par);
    cudaGetSymbolAddress((void**)&bcT,  g_bcT);
    cudaGetSymbolAddress((void**)&scan, g_scan);
    cudaGetSymbolAddress((void**)&x1,   g_x1);
    cudaGetSymbolAddress((void**)&h1h,  g_h1h);  cudaGetSymbolAddress((void**)&h1l, g_h1l);
    cudaGetSymbolAddress((void**)&ygh,  g_ygh);
    cudaGetSymbolAddress((void**)&h2h,  g_h2h);
    cudaGetSymbolAddress((void**)&ffh,  g_ffh);
    cudaGetSymbolAddress((void**)&win,  g_win);
    cudaGetSymbolAddress((void**)&wo,   g_wo);
    cudaGetSymbolAddress((void**)&w1,   g_w1);
    cudaGetSymbolAddress((void**)&w2,   g_w2);
    cudaGetSymbolAddress((void**)&wth,  g_wth);
    cudaGetSymbolAddress((void**)&wtl,  g_wtl);

    cudaFuncSetAttribute(gemm_mma1, cudaFuncAttributeMaxDynamicSharedMemorySize, GEMM1_SMEM);
    cudaFuncSetAttribute(gemm_mma3, cudaFuncAttributeMaxDynamicSharedMemorySize, GEMM3_SMEM);

    // weight fp16 conversion (idempotent)
    cvt4_kernel<<<(PROJ_OUT * 1024 / 4 + 255) / 256, 256>>>((const float4*)w_in,
        (__half2*)win, PROJ_OUT * 1024 / 4);
    cvt4_kernel<<<(1024 * 2048 / 4 + 255) / 256, 256>>>((const float4*)w_out,
        (__half2*)wo, 1024 * 2048 / 4);
    cvt4_kernel<<<(4096 * 1024 / 4 + 255) / 256, 256>>>((const float4*)ff_w1,
        (__half2*)w1, 4096 * 1024 / 4);
    cvt4_kernel<<<(1024 * 4096 / 4 + 255) / 256, 256>>>((const float4*)ff_w2,
        (__half2*)w2, 1024 * 4096 / 4);
    // hi/lo split of w_in tail rows (scan-parameter columns)
    split4_kernel<<<(128 * 1024 / 4 + 255) / 256, 256>>>(
        (const float4*)(w_in + (size_t)4096 * 1024), (__half2*)wth, (__half2*)wtl, 128 * 1024 / 4);

    // 1. h1 = rmsnorm(x) (fp16 hi+lo; lo used only by the 3-product tail)
    rmsnorm_split_kernel<<<BT, 256>>>(x, norm1_w, h1h, h1l);
    // 2a. proj[:, :4096] = h1 @ w_in[:4096]^T  (1-product)
    gemm_mma1<<<dim3(32, BT / 128), 256, GEMM1_SMEM>>>(h1h, win, nullptr, nullptr,
                                                       proj, nullptr, PROJ_OUT, DMODEL, 1);
    // 2b. proj[:, 4096:] = h1 @ w_in[4096:]^T  (3-product, scan params)
    gemm_mma3<<<dim3(1, BT / 128), 256, GEMM3_SMEM>>>(h1h, h1l, wth, wtl,
                                                      proj + 4096, PROJ_OUT, DMODEL);
    // 3. fused conv+silu / params / bcpack (vectorized conv)
    prep_kernel<<<BT, 256>>>(proj, conv_w, conv_b, val, par, bcT);
    // 4. scan (R14 exact)
    scan_kernel<<<2 * BQ * NHEADS, 512>>>(bcT, par, val, scan);
    // 5. yg = rmsnorm(scan * silu(gate)) (fp16 hi only)
    gated_norm_kernel<<<BT, 256>>>(proj, scan, out_nw, ygh);
    // 6. x1 = x + yg @ w_out^T  (1-product)
    gemm_mma1<<<dim3(DMODEL / 128, BT / 128), 256, GEMM1_SMEM>>>(ygh, wo, nullptr, x,
                                                    x1, nullptr, DMODEL, DINNER, 1);
    // 7. h2 = rmsnorm(x1) (fp16 hi only)
    rmsnorm_split_kernel<<<BT, 256>>>(x1, norm2_w, h2h, nullptr);
    // 8. ffh = fp16(gelu(h2 @ ff_w1^T + b1))  (1-product)
    gemm_mma1<<<dim3(DFF / 128, BT / 128), 256, GEMM1_SMEM>>>(h2h, w1, ff_b1, nullptr,
                                                 nullptr, ffh, DFF, DMODEL, 2);
    // 9. out = x1 + ffh @ ff_w2^T + b2  (1-product)
    gemm_mma1<<<dim3(DMODEL / 128, BT / 128), 256, GEMM1_SMEM>>>(ffh, w2, ff_b2, x1,
                                                    out, nullptr, DMODEL, DFF, 1);
}